// round 2
// baseline (speedup 1.0000x reference)
#include <cuda_runtime.h>
#include <cstdint>

#define M_NODES 100000
#define DD      128
#define E_EDGES 1600000
#define KTOT    384
#define NGRAPH  16

// ---------------- device scratch (static: allocation-free) ----------------
__device__ __align__(16) float g_sum[(size_t)M_NODES * DD]; // 51.2 MB edge sums
__device__ float g_cnt[M_NODES];
__device__ int   g_is64; // 1 if index tensors are int64, 0 if int32

// ---------------- f32x2 packed-math helpers (full-rate fp32 on sm_103a) ----
__device__ __forceinline__ unsigned long long splat2(float x) {
    unsigned long long r;
    asm("mov.b64 %0, {%1, %1};" : "=l"(r) : "f"(x));
    return r;
}
__device__ __forceinline__ unsigned long long fma2(unsigned long long a,
                                                   unsigned long long b,
                                                   unsigned long long c) {
    unsigned long long d;
    asm("fma.rn.f32x2 %0, %1, %2, %3;" : "=l"(d) : "l"(a), "l"(b), "l"(c));
    return d;
}
__device__ __forceinline__ float2 unpack2(unsigned long long v) {
    float2 r;
    asm("mov.b64 {%0, %1}, %2;" : "=f"(r.x), "=f"(r.y) : "l"(v));
    return r;
}

// ---------------- kernel 0: zero the accumulators --------------------------
__global__ void zero_kernel() {
    const int stride = gridDim.x * blockDim.x;
    int t = blockIdx.x * blockDim.x + threadIdx.x;
    const long long n = (long long)M_NODES * DD;
    for (long long i = t; i < n; i += stride) g_sum[i] = 0.0f;
    for (int i = t; i < M_NODES; i += stride) g_cnt[i] = 0.0f;
}

// ---------------- kernel 0b: detect int64 vs int32 index dtype -------------
__global__ void detect_kernel(const unsigned int* ei_words) {
    __shared__ unsigned int s;
    if (threadIdx.x == 0) s = 0u;
    __syncthreads();
    unsigned int v = 0u;
    for (int i = threadIdx.x; i < 8192; i += blockDim.x) v |= ei_words[2 * i + 1];
    atomicOr(&s, v);
    __syncthreads();
    if (threadIdx.x == 0) g_is64 = (s == 0u) ? 1 : 0;
}

// ---------------- kernel 1: scatter-add edges (one warp per edge) ----------
__global__ void scatter_kernel(const float* __restrict__ edge_attr,
                               const void* __restrict__ edge_index) {
    const int lane   = threadIdx.x & 31;
    const int warp   = (blockIdx.x * blockDim.x + threadIdx.x) >> 5;
    const int nwarps = (gridDim.x * blockDim.x) >> 5;
    const int is64   = g_is64;
    const long long* ei64 = (const long long*)edge_index;
    const int*       ei32 = (const int*)edge_index;

    for (int e = warp; e < E_EDGES; e += nwarps) {
        int dest = 0;
        if (lane == 0)
            dest = is64 ? (int)ei64[(long long)E_EDGES + e] : ei32[E_EDGES + e];
        dest = __shfl_sync(0xffffffffu, dest, 0);

        float4 v = *(const float4*)(edge_attr + (long long)e * DD + lane * 4);
        float* p = g_sum + (long long)dest * DD + lane * 4;
        asm volatile("red.global.add.v4.f32 [%0], {%1, %2, %3, %4};"
                     :: "l"(p), "f"(v.x), "f"(v.y), "f"(v.z), "f"(v.w)
                     : "memory");
        if (lane == 0) atomicAdd(&g_cnt[dest], 1.0f);
    }
}

// ---------------- kernel 2: fused concat + MLP (both GEMMs) ----------------
// 512 threads, thread tile 4 rows x 8 cols. Register-prefetch pipeline for
// the per-tile global loads.
#define BM 128
#define BN 128
#define BK 16
#define THREADS 512
#define HS_STRIDE 132

// dynamic smem layout (floats):
//   As  [BK][BM]       : 2048
//   Bs  [BK][BN]       : 2048
//   W2s [128][128]     : 16384
//   Hs  [BM][HS_STRIDE]: 16896
#define SMEM_FLOATS (2048 + 2048 + 16384 + 16896)

extern __shared__ float smem_f[];

__global__ __launch_bounds__(THREADS, 1)
void fused_mlp_kernel(const float* __restrict__ x,
                      const float* __restrict__ u,
                      const float* __restrict__ W1,
                      const float* __restrict__ b1,
                      const float* __restrict__ W2,
                      const float* __restrict__ b2,
                      const void*  __restrict__ batch_ptr,
                      float* __restrict__ out) {
    float* As  = smem_f;                 // As[kk*BM + m] (transposed)
    float* Bs  = smem_f + 2048;          // Bs[kk*BN + n]
    float* W2s = smem_f + 4096;          // W2s[k*128 + n]
    float* Hs  = smem_f + 4096 + 16384;  // Hs[m*HS_STRIDE + k]

    const int tid  = threadIdx.x;
    const int tx   = tid & 15;           // col group (8 cols)
    const int ty   = tid >> 4;           // row group (4 rows)
    const int row0 = ty * 4;
    const int col0 = tx * 8;
    const int gm0  = blockIdx.x * BM;

    const int is64 = g_is64;
    const long long* bat64 = (const long long*)batch_ptr;
    const int*       bat32 = (const int*)batch_ptr;

    // A prefetch mapping: r = row in tile, q = k-quad
    const int pr = tid >> 2;             // 0..127
    const int pq = tid & 3;              // 0..3
    const int pm = gm0 + pr;
    // B prefetch mapping
    const int br = tid >> 5;             // 0..15
    const int bq = tid & 31;             // 0..31

    // stage W2 into smem (overlaps with everything up to phase B)
    #pragma unroll
    for (int i = 0; i < 8; i++)
        ((float4*)W2s)[tid + i * THREADS] = ((const float4*)W2)[tid + i * THREADS];

    // ---- prefetch tile 0 ----
    auto load_a = [&](int kbase) -> float4 {
        int k = kbase + pq * 4;
        float4 v = make_float4(0.f, 0.f, 0.f, 0.f);
        if (pm < M_NODES) {
            if (k < 128) {
                v = *(const float4*)(x + (long long)pm * DD + k);
            } else if (k < 256) {
                v = *(const float4*)(g_sum + (long long)pm * DD + (k - 128));
                float inv = 1.0f / fmaxf(g_cnt[pm], 1.0f);
                v.x *= inv; v.y *= inv; v.z *= inv; v.w *= inv;
            } else {
                long long b = is64 ? bat64[pm] : (long long)bat32[pm];
                v = *(const float4*)(u + b * DD + (k - 256));
            }
        }
        return v;
    };

    float4 aReg = load_a(0);
    float4 bReg = ((const float4*)(W1 + (long long)br * DD))[bq];

    unsigned long long acc[4][4];
    #pragma unroll
    for (int i = 0; i < 4; i++)
        #pragma unroll
        for (int j = 0; j < 4; j++) acc[i][j] = 0ull;

    // ---------------- Phase A: H = relu(feats @ W1 + b1) ----------------
    #pragma unroll 1
    for (int t = 0; t < KTOT / BK; t++) {
        // commit staged registers to smem
        {
            int kk = pq * 4;
            As[(kk + 0) * BM + pr] = aReg.x;
            As[(kk + 1) * BM + pr] = aReg.y;
            As[(kk + 2) * BM + pr] = aReg.z;
            As[(kk + 3) * BM + pr] = aReg.w;
            ((float4*)(Bs + br * BN))[bq] = bReg;
        }
        __syncthreads();

        // prefetch next tile (overlaps with compute below)
        if (t + 1 < KTOT / BK) {
            aReg = load_a((t + 1) * BK);
            bReg = ((const float4*)(W1 + (long long)((t + 1) * BK + br) * DD))[bq];
        }

        #pragma unroll
        for (int kk = 0; kk < BK; kk++) {
            float4 av = *(const float4*)(As + kk * BM + row0);
            ulonglong2 bA = *(const ulonglong2*)(Bs + kk * BN + col0);
            ulonglong2 bB = *(const ulonglong2*)(Bs + kk * BN + col0 + 4);
            unsigned long long bv[4] = {bA.x, bA.y, bB.x, bB.y};
            float a[4] = {av.x, av.y, av.z, av.w};
            #pragma unroll
            for (int i = 0; i < 4; i++) {
                unsigned long long ai = splat2(a[i]);
                #pragma unroll
                for (int j = 0; j < 4; j++) acc[i][j] = fma2(ai, bv[j], acc[i][j]);
            }
        }
        __syncthreads();
    }

    // bias + relu, park H in SMEM
    float b1v[8];
    #pragma unroll
    for (int j = 0; j < 8; j++) b1v[j] = b1[col0 + j];
    #pragma unroll
    for (int i = 0; i < 4; i++) {
        #pragma unroll
        for (int jp = 0; jp < 4; jp++) {
            float2 p = unpack2(acc[i][jp]);
            float h0 = fmaxf(p.x + b1v[2 * jp], 0.0f);
            float h1 = fmaxf(p.y + b1v[2 * jp + 1], 0.0f);
            *(float2*)(Hs + (row0 + i) * HS_STRIDE + col0 + 2 * jp) =
                make_float2(h0, h1);
        }
    }
    __syncthreads();

    // ---------------- Phase B: out = H @ W2 + b2 ----------------
    #pragma unroll
    for (int i = 0; i < 4; i++)
        #pragma unroll
        for (int j = 0; j < 4; j++) acc[i][j] = 0ull;

    #pragma unroll 4
    for (int kk = 0; kk < 128; kk++) {
        ulonglong2 bA = *(const ulonglong2*)(W2s + kk * 128 + col0);
        ulonglong2 bB = *(const ulonglong2*)(W2s + kk * 128 + col0 + 4);
        unsigned long long bv[4] = {bA.x, bA.y, bB.x, bB.y};
        #pragma unroll
        for (int i = 0; i < 4; i++) {
            unsigned long long ai = splat2(Hs[(row0 + i) * HS_STRIDE + kk]);
            #pragma unroll
            for (int j = 0; j < 4; j++) acc[i][j] = fma2(ai, bv[j], acc[i][j]);
        }
    }

    float b2v[8];
    #pragma unroll
    for (int j = 0; j < 8; j++) b2v[j] = b2[col0 + j];
    #pragma unroll
    for (int i = 0; i < 4; i++) {
        int m = gm0 + row0 + i;
        if (m < M_NODES) {
            float2 p0 = unpack2(acc[i][0]);
            float2 p1 = unpack2(acc[i][1]);
            float2 p2 = unpack2(acc[i][2]);
            float2 p3 = unpack2(acc[i][3]);
            float4 o0 = make_float4(p0.x + b2v[0], p0.y + b2v[1],
                                    p1.x + b2v[2], p1.y + b2v[3]);
            float4 o1 = make_float4(p2.x + b2v[4], p2.y + b2v[5],
                                    p3.x + b2v[6], p3.y + b2v[7]);
            *(float4*)(out + (long long)m * DD + col0)     = o0;
            *(float4*)(out + (long long)m * DD + col0 + 4) = o1;
        }
    }
}

// ---------------- host launcher --------------------------------------------
extern "C" void kernel_launch(void* const* d_in, const int* in_sizes, int n_in,
                              void* d_out, int out_size) {
    const float* x         = (const float*)d_in[0];
    const float* edge_attr = (const float*)d_in[1];
    const float* u         = (const float*)d_in[2];
    const float* W1        = (const float*)d_in[3];
    const float* b1        = (const float*)d_in[4];
    const float* W2        = (const float*)d_in[5];
    const float* b2        = (const float*)d_in[6];
    const void*  edge_index = d_in[7];
    const void*  batch      = d_in[8];
    float* out = (float*)d_out;

    static bool attr_set = false;
    if (!attr_set) {
        cudaFuncSetAttribute(fused_mlp_kernel,
                             cudaFuncAttributeMaxDynamicSharedMemorySize,
                             SMEM_FLOATS * sizeof(float));
        attr_set = true;
    }

    zero_kernel<<<2048, 256>>>();
    detect_kernel<<<1, 256>>>((const unsigned int*)edge_index);
    scatter_kernel<<<1184, 256>>>(edge_attr, edge_index);

    int nblocks = (M_NODES + BM - 1) / BM;  // 782
    fused_mlp_kernel<<<nblocks, THREADS, SMEM_FLOATS * sizeof(float)>>>(
        x, u, W1, b1, W2, b2, batch, out);
}

// round 4
// speedup vs baseline: 1.6235x; 1.6235x over previous
#include <cuda_runtime.h>
#include <cuda_bf16.h>
#include <cstdint>

#define M_NODES 100000
#define DD      128
#define E_EDGES 1600000
#define NGRAPH  16

// expanded-K tile geometry: 16 orig k -> 48 expanded (3 slices), row pitch 56 bf16 = 112B
#define NC1 24      // GEMM1 chunks (384/16)
#define NC2 8       // GEMM2 chunks (128/16)
#define TILE_B 14336   // 128 rows * 112B
#define ROWP 112

// ---------------- device scratch (static: allocation-free) ----------------
__device__ __align__(16) float g_sum[(size_t)M_NODES * DD];
__device__ float g_cnt[M_NODES];
__device__ int   g_is64;
// pre-split, pre-transposed, pre-interleaved weights (slices h,l,h), row pitch 56
__device__ __align__(16) unsigned short Bexp1[NC1 * 128 * 56];
__device__ __align__(16) unsigned short Bexp2[NC2 * 128 * 56];

// ---------------- PTX helpers ----------------------------------------------
__device__ __forceinline__ uint32_t smem_u32(const void* p) {
    uint32_t a;
    asm("{ .reg .u64 t; cvta.to.shared.u64 t, %1; cvt.u32.u64 %0, t; }"
        : "=r"(a) : "l"(p));
    return a;
}
#define CP16(dst, src) \
    asm volatile("cp.async.ca.shared.global [%0], [%1], 16;" :: "r"(dst), "l"(src))
#define CP_COMMIT() asm volatile("cp.async.commit_group;" ::: "memory")
#define CP_WAIT1()  asm volatile("cp.async.wait_group 1;" ::: "memory")
#define CP_WAIT0()  asm volatile("cp.async.wait_group 0;" ::: "memory")
#define LDM_X4(r0, r1, r2, r3, a) \
    asm volatile("ldmatrix.sync.aligned.m8n8.x4.shared.b16 {%0,%1,%2,%3}, [%4];" \
                 : "=r"(r0), "=r"(r1), "=r"(r2), "=r"(r3) : "r"(a))
#define MMA_BF16(d, a, b0, b1) \
    asm volatile("mma.sync.aligned.m16n8k16.row.col.f32.bf16.bf16.f32 " \
                 "{%0,%1,%2,%3}, {%4,%5,%6,%7}, {%8,%9}, {%0,%1,%2,%3};" \
                 : "+f"((d)[0]), "+f"((d)[1]), "+f"((d)[2]), "+f"((d)[3]) \
                 : "r"((a)[0]), "r"((a)[1]), "r"((a)[2]), "r"((a)[3]), \
                   "r"(b0), "r"(b1))

// split pair of fp32 into packed bf16x2 hi + packed bf16x2 lo (mem order: v0 low)
__device__ __forceinline__ void split2(float v0, float v1,
                                       uint32_t& hp, uint32_t& lp) {
    uint32_t h2;
    asm("cvt.rn.bf16x2.f32 %0, %1, %2;" : "=r"(h2) : "f"(v1), "f"(v0));
    float h0 = __uint_as_float(h2 << 16);
    float h1 = __uint_as_float(h2 & 0xFFFF0000u);
    float l0 = v0 - h0, l1 = v1 - h1;
    asm("cvt.rn.bf16x2.f32 %0, %1, %2;" : "=r"(lp) : "f"(l1), "f"(l0));
    hp = h2;
}

// ---------------- kernel 0: zero the accumulators --------------------------
__global__ void zero_kernel() {
    const int stride = gridDim.x * blockDim.x;
    int t = blockIdx.x * blockDim.x + threadIdx.x;
    float4 z = make_float4(0.f, 0.f, 0.f, 0.f);
    const int n4 = M_NODES * DD / 4;
    for (int i = t; i < n4; i += stride) ((float4*)g_sum)[i] = z;
    for (int i = t; i < M_NODES; i += stride) g_cnt[i] = 0.0f;
}

// ---------------- kernel 0b: detect int64 vs int32 index dtype -------------
__global__ void detect_kernel(const unsigned int* ei_words) {
    __shared__ unsigned int s;
    if (threadIdx.x == 0) s = 0u;
    __syncthreads();
    unsigned int v = 0u;
    for (int i = threadIdx.x; i < 8192; i += blockDim.x) v |= ei_words[2 * i + 1];
    atomicOr(&s, v);
    __syncthreads();
    if (threadIdx.x == 0) g_is64 = (s == 0u) ? 1 : 0;
}

// ---------------- kernel 0c: split+transpose+interleave weights ------------
__global__ void prep_kernel(const float* __restrict__ W1,
                            const float* __restrict__ W2) {
    int i = blockIdx.x * blockDim.x + threadIdx.x;
    if (i < NC1 * 128 * 16) {
        int c = i >> 11;            // /(128*16)
        int n = (i >> 4) & 127;
        int k = i & 15;
        float w = W1[(c * 16 + k) * 128 + n];
        unsigned short h;
        asm("cvt.rn.bf16.f32 %0, %1;" : "=h"(h) : "f"(w));
        float hf = __uint_as_float(((uint32_t)h) << 16);
        float l = w - hf;
        unsigned short lo;
        asm("cvt.rn.bf16.f32 %0, %1;" : "=h"(lo) : "f"(l));
        unsigned short* row = Bexp1 + ((size_t)c * 128 + n) * 56;
        row[k] = h; row[16 + k] = lo; row[32 + k] = h;
    }
    if (i < NC2 * 128 * 16) {
        int c = i >> 11;
        int n = (i >> 4) & 127;
        int k = i & 15;
        float w = W2[(c * 16 + k) * 128 + n];
        unsigned short h;
        asm("cvt.rn.bf16.f32 %0, %1;" : "=h"(h) : "f"(w));
        float hf = __uint_as_float(((uint32_t)h) << 16);
        float l = w - hf;
        unsigned short lo;
        asm("cvt.rn.bf16.f32 %0, %1;" : "=h"(lo) : "f"(l));
        unsigned short* row = Bexp2 + ((size_t)c * 128 + n) * 56;
        row[k] = h; row[16 + k] = lo; row[32 + k] = h;
    }
}

// ---------------- kernel 1: scatter-add edges (one warp per edge) ----------
__global__ void scatter_kernel(const float* __restrict__ edge_attr,
                               const void* __restrict__ edge_index) {
    const int lane   = threadIdx.x & 31;
    const int warp   = (blockIdx.x * blockDim.x + threadIdx.x) >> 5;
    const int nwarps = (gridDim.x * blockDim.x) >> 5;
    const int is64   = g_is64;
    const long long* ei64 = (const long long*)edge_index;
    const int*       ei32 = (const int*)edge_index;

    for (int e = warp; e < E_EDGES; e += nwarps) {
        int dest = 0;
        if (lane == 0)
            dest = is64 ? (int)ei64[(long long)E_EDGES + e] : ei32[E_EDGES + e];
        dest = __shfl_sync(0xffffffffu, dest, 0);

        float4 v = *(const float4*)(edge_attr + (long long)e * DD + lane * 4);
        float* p = g_sum + (long long)dest * DD + lane * 4;
        asm volatile("red.global.add.v4.f32 [%0], {%1, %2, %3, %4};"
                     :: "l"(p), "f"(v.x), "f"(v.y), "f"(v.z), "f"(v.w)
                     : "memory");
        if (lane == 0) atomicAdd(&g_cnt[dest], 1.0f);
    }
}

// ---------------- kernel 2: fused concat + 2x GEMM via mma.sync bf16 -------
// CTA = 128 rows x 128 cols, 8 warps (warpM = wid>>1 in 0..3, warpN = wid&1).
// smem: stage pool [0, 2*28672) : per stage {A tile, B tile}
//       H region   [57344, 57344+8*14336)
//       b1s/b2s at 172032
#define THREADS 256
#define STAGE_B 28672
#define HBASE   57344
#define CTRL    172032
#define SMEM_TOTAL (CTRL + 1024)

__global__ __launch_bounds__(THREADS, 1)
void fused_mlp_mma(const float* __restrict__ x,
                   const float* __restrict__ u,
                   const float* __restrict__ b1,
                   const float* __restrict__ b2,
                   const void*  __restrict__ batch_ptr,
                   float* __restrict__ out) {
    extern __shared__ char smem[];
    const uint32_t sbase = smem_u32(smem);
    const int tid   = threadIdx.x;
    const int wid   = tid >> 5;
    const int lane  = tid & 31;
    const int warpM = wid >> 1;
    const int warpN = wid & 1;
    const int gm0   = blockIdx.x * 128;

    float* b1s = (float*)(smem + CTRL);
    float* b2s = (float*)(smem + CTRL + 512);
    if (tid < 128) b1s[tid] = b1[tid];
    else b2s[tid - 128] = b2[tid - 128];

    // ---- per-thread A-fill mapping: row = tid>>1, k-half = tid&1 ----
    const int fr = tid >> 1;
    const int hh = tid & 1;
    const int fm = gm0 + fr;
    const bool valid = fm < M_NODES;
    float inv = 1.0f;
    long long ub = 0;
    if (valid) {
        inv = 1.0f / fmaxf(g_cnt[fm], 1.0f);
        ub  = g_is64 ? ((const long long*)batch_ptr)[fm]
                     : (long long)((const int*)batch_ptr)[fm];
    }
    const uint32_t a_fill_off = (uint32_t)fr * ROWP + hh * 16;

    // ---- ldmatrix lane offsets ----
    const uint32_t a_lane = ((lane & 7) + 8 * ((lane >> 3) & 1)) * ROWP +
                            (lane >> 4) * 16;
    const uint32_t b_lane = ((lane & 7) + 8 * (lane >> 4)) * ROWP +
                            ((lane >> 3) & 1) * 16;

    // A-fill: gather feats chunk c into stage, bf16 split, slices {h,h,l}
    auto fill_A = [&](int c, uint32_t stage) {
        float4 v0 = make_float4(0.f, 0.f, 0.f, 0.f), v1 = v0;
        if (valid) {
            const float* src;
            if (c < 8) src = x + (long long)fm * DD + c * 16 + hh * 8;
            else if (c < 16) src = g_sum + (long long)fm * DD + (c - 8) * 16 + hh * 8;
            else src = u + ub * DD + (c - 16) * 16 + hh * 8;
            v0 = ((const float4*)src)[0];
            v1 = ((const float4*)src)[1];
            if (c >= 8 && c < 16) {
                v0.x *= inv; v0.y *= inv; v0.z *= inv; v0.w *= inv;
                v1.x *= inv; v1.y *= inv; v1.z *= inv; v1.w *= inv;
            }
        }
        uint4 hp, lp;
        split2(v0.x, v0.y, hp.x, lp.x);
        split2(v0.z, v0.w, hp.y, lp.y);
        split2(v1.x, v1.y, hp.z, lp.z);
        split2(v1.z, v1.w, hp.w, lp.w);
        char* dst = smem + stage + a_fill_off;
        *(uint4*)(dst)      = hp;   // slice 0 (hi)
        *(uint4*)(dst + 32) = hp;   // slice 1 (hi)
        *(uint4*)(dst + 64) = lp;   // slice 2 (lo)
    };
    // B-fill: 16B cp.async copies of pre-interleaved weights
    auto fill_B = [&](const unsigned short* Bsrc, int c, uint32_t stage_b) {
        const char* base = (const char*)(Bsrc + (size_t)c * 128 * 56);
        #pragma unroll
        for (int i = 0; i < 3; i++) {
            int seg = tid + i * THREADS;         // 0..767
            int row = seg / 6, off = (seg % 6) * 16;
            CP16(sbase + stage_b + row * ROWP + off, base + row * ROWP + off);
        }
    };

    float acc[2][8][4];
    #pragma unroll
    for (int mt = 0; mt < 2; mt++)
        #pragma unroll
        for (int nt = 0; nt < 8; nt++)
            #pragma unroll
            for (int e = 0; e < 4; e++) acc[mt][nt][e] = 0.f;

    auto compute = [&](uint32_t Aoff, uint32_t Boff) {
        #pragma unroll
        for (int s = 0; s < 3; s++) {
            uint32_t a0[4], a1[4], bf[4][4];
            LDM_X4(a0[0], a0[1], a0[2], a0[3],
                   sbase + Aoff + (warpM * 32 + 0) * ROWP + a_lane + s * 32);
            LDM_X4(a1[0], a1[1], a1[2], a1[3],
                   sbase + Aoff + (warpM * 32 + 16) * ROWP + a_lane + s * 32);
            #pragma unroll
            for (int p = 0; p < 4; p++)
                LDM_X4(bf[p][0], bf[p][1], bf[p][2], bf[p][3],
                       sbase + Boff + (warpN * 64 + p * 16) * ROWP + b_lane + s * 32);
            #pragma unroll
            for (int nt = 0; nt < 8; nt++) {
                uint32_t bb0 = bf[nt >> 1][(nt & 1) * 2];
                uint32_t bb1 = bf[nt >> 1][(nt & 1) * 2 + 1];
                MMA_BF16(acc[0][nt], a0, bb0, bb1);
                MMA_BF16(acc[1][nt], a1, bb0, bb1);
            }
        }
    };

    // ================= GEMM1 =================
    fill_A(0, 0);
    fill_B(Bexp1, 0, TILE_B);
    CP_COMMIT();
    #pragma unroll 1
    for (int c = 0; c < NC1; c++) {
        const uint32_t st = (c & 1) * STAGE_B;
        __syncthreads();                       // prev compute done -> next stage free
        if (c + 1 < NC1) {
            const uint32_t nst = ((c + 1) & 1) * STAGE_B;
            fill_A(c + 1, nst);
            fill_B(Bexp1, c + 1, nst + TILE_B);
            CP_COMMIT();
            CP_WAIT1();
        } else {
            CP_WAIT0();
        }
        __syncthreads();                       // stage c visible to all
        compute(st, st + TILE_B);
    }

    // ============ epilogue 1: H = relu(D1+b1) -> H region (expanded) =======
    __syncthreads();                           // all GEMM1 reads done; stages free
    fill_B(Bexp2, 0, 0);        CP_COMMIT();   // B2 chunk0 -> stage0
    fill_B(Bexp2, 1, STAGE_B);  CP_COMMIT();   // B2 chunk1 -> stage1

    #pragma unroll
    for (int mt = 0; mt < 2; mt++) {
        #pragma unroll
        for (int nt = 0; nt < 8; nt++) {
            int col = warpN * 64 + nt * 8 + (lane & 3) * 2;
            float bv0 = b1s[col], bv1 = b1s[col + 1];
            int cch = col >> 4, k0 = col & 15;
            uint32_t hb = HBASE + cch * TILE_B + k0 * 2;
            #pragma unroll
            for (int rr = 0; rr < 2; rr++) {
                int row = warpM * 32 + mt * 16 + (lane >> 2) + rr * 8;
                float v0 = fmaxf(acc[mt][nt][rr * 2 + 0] + bv0, 0.f);
                float v1 = fmaxf(acc[mt][nt][rr * 2 + 1] + bv1, 0.f);
                uint32_t hp, lp;
                split2(v0, v1, hp, lp);
                char* dst = smem + hb + row * ROWP;
                *(uint32_t*)(dst)      = hp;
                *(uint32_t*)(dst + 32) = hp;
                *(uint32_t*)(dst + 64) = lp;
                acc[mt][nt][rr * 2 + 0] = 0.f;   // reset for GEMM2
                acc[mt][nt][rr * 2 + 1] = 0.f;
            }
        }
    }
    CP_WAIT1();                                 // B2 chunk0 arrived
    __syncthreads();                            // H + B2 stage0 visible

    // ================= GEMM2 =================
    #pragma unroll 1
    for (int c = 0; c < NC2; c++) {
        compute(HBASE + c * TILE_B, (c & 1) * STAGE_B);
        __syncthreads();                        // stage c&1 free
        if (c + 2 < NC2) {
            fill_B(Bexp2, c + 2, (c & 1) * STAGE_B);
            CP_COMMIT();
            CP_WAIT1();
        } else {
            CP_WAIT0();
        }
        __syncthreads();                        // next stage visible
    }

    // ============ epilogue 2: out = D2 + b2 ============
    #pragma unroll
    for (int mt = 0; mt < 2; mt++) {
        #pragma unroll
        for (int nt = 0; nt < 8; nt++) {
            int col = warpN * 64 + nt * 8 + (lane & 3) * 2;
            float bv0 = b2s[col], bv1 = b2s[col + 1];
            #pragma unroll
            for (int rr = 0; rr < 2; rr++) {
                int m = gm0 + warpM * 32 + mt * 16 + (lane >> 2) + rr * 8;
                if (m < M_NODES) {
                    float2 o = make_float2(acc[mt][nt][rr * 2 + 0] + bv0,
                                           acc[mt][nt][rr * 2 + 1] + bv1);
                    *(float2*)(out + (long long)m * DD + col) = o;
                }
            }
        }
    }
}

// ---------------- host launcher --------------------------------------------
extern "C" void kernel_launch(void* const* d_in, const int* in_sizes, int n_in,
                              void* d_out, int out_size) {
    const float* x         = (const float*)d_in[0];
    const float* edge_attr = (const float*)d_in[1];
    const float* u         = (const float*)d_in[2];
    const float* W1        = (const float*)d_in[3];
    const float* b1        = (const float*)d_in[4];
    const float* W2        = (const float*)d_in[5];
    const float* b2        = (const float*)d_in[6];
    const void*  edge_index = d_in[7];
    const void*  batch      = d_in[8];
    float* out = (float*)d_out;

    static bool attr_set = false;
    if (!attr_set) {
        cudaFuncSetAttribute(fused_mlp_mma,
                             cudaFuncAttributeMaxDynamicSharedMemorySize,
                             SMEM_TOTAL);
        attr_set = true;
    }

    zero_kernel<<<2048, 256>>>();
    detect_kernel<<<1, 256>>>((const unsigned int*)edge_index);
    prep_kernel<<<192, 256>>>(W1, W2);
    scatter_kernel<<<1184, 256>>>(edge_attr, edge_index);

    int nblocks = (M_NODES + 127) / 128;  // 782
    fused_mlp_mma<<<nblocks, THREADS, SMEM_TOTAL>>>(x, u, b1, b2, batch, out);
}

// round 5
// speedup vs baseline: 1.7575x; 1.0826x over previous
#include <cuda_runtime.h>
#include <cuda_bf16.h>
#include <cstdint>

#define M_NODES 100000
#define DD      128
#define E_EDGES 1600000
#define NGRAPH  16

// expanded-K tile geometry: 16 orig k -> 48 expanded (3 slices), row pitch 56 bf16 = 112B
#define NC1 24      // GEMM1 chunks (384/16)
#define NC2 8       // GEMM2 chunks (128/16)
#define TILE_B 14336   // 128 rows * 112B
#define ROWP 112

// ---------------- device scratch (static: allocation-free) ----------------
__device__ __align__(16) float g_sum[(size_t)M_NODES * DD];
__device__ float g_cnt[M_NODES];
__device__ int   g_is64;
// pre-split, pre-transposed, pre-interleaved weights (slices h,l,h), row pitch 56
__device__ __align__(16) unsigned short Bexp1[NC1 * 128 * 56];
__device__ __align__(16) unsigned short Bexp2[NC2 * 128 * 56];

// ---------------- PTX helpers ----------------------------------------------
__device__ __forceinline__ uint32_t smem_u32(const void* p) {
    uint32_t a;
    asm("{ .reg .u64 t; cvta.to.shared.u64 t, %1; cvt.u32.u64 %0, t; }"
        : "=r"(a) : "l"(p));
    return a;
}
#define CP16(dst, src) \
    asm volatile("cp.async.ca.shared.global [%0], [%1], 16;" :: "r"(dst), "l"(src))
#define CP_COMMIT() asm volatile("cp.async.commit_group;" ::: "memory")
#define CP_WAIT1()  asm volatile("cp.async.wait_group 1;" ::: "memory")
#define CP_WAIT0()  asm volatile("cp.async.wait_group 0;" ::: "memory")
#define LDM_X4(r0, r1, r2, r3, a) \
    asm volatile("ldmatrix.sync.aligned.m8n8.x4.shared.b16 {%0,%1,%2,%3}, [%4];" \
                 : "=r"(r0), "=r"(r1), "=r"(r2), "=r"(r3) : "r"(a))
#define MMA_BF16(d, a, b0, b1) \
    asm volatile("mma.sync.aligned.m16n8k16.row.col.f32.bf16.bf16.f32 " \
                 "{%0,%1,%2,%3}, {%4,%5,%6,%7}, {%8,%9}, {%0,%1,%2,%3};" \
                 : "+f"((d)[0]), "+f"((d)[1]), "+f"((d)[2]), "+f"((d)[3]) \
                 : "r"((a)[0]), "r"((a)[1]), "r"((a)[2]), "r"((a)[3]), \
                   "r"(b0), "r"(b1))

// split pair of fp32 into packed bf16x2 hi + packed bf16x2 lo (mem order: v0 low)
__device__ __forceinline__ void split2(float v0, float v1,
                                       uint32_t& hp, uint32_t& lp) {
    uint32_t h2;
    asm("cvt.rn.bf16x2.f32 %0, %1, %2;" : "=r"(h2) : "f"(v1), "f"(v0));
    float h0 = __uint_as_float(h2 << 16);
    float h1 = __uint_as_float(h2 & 0xFFFF0000u);
    float l0 = v0 - h0, l1 = v1 - h1;
    asm("cvt.rn.bf16x2.f32 %0, %1, %2;" : "=r"(lp) : "f"(l1), "f"(l0));
    hp = h2;
}

// ---------------- kernel 0: zero the accumulators --------------------------
__global__ void zero_kernel() {
    const int stride = gridDim.x * blockDim.x;
    int t = blockIdx.x * blockDim.x + threadIdx.x;
    float4 z = make_float4(0.f, 0.f, 0.f, 0.f);
    const int n4 = M_NODES * DD / 4;
    for (int i = t; i < n4; i += stride) ((float4*)g_sum)[i] = z;
    for (int i = t; i < M_NODES; i += stride) g_cnt[i] = 0.0f;
}

// ---------------- kernel 0b: detect int64 vs int32 index dtype -------------
__global__ void detect_kernel(const unsigned int* ei_words) {
    __shared__ unsigned int s;
    if (threadIdx.x == 0) s = 0u;
    __syncthreads();
    unsigned int v = 0u;
    for (int i = threadIdx.x; i < 8192; i += blockDim.x) v |= ei_words[2 * i + 1];
    atomicOr(&s, v);
    __syncthreads();
    if (threadIdx.x == 0) g_is64 = (s == 0u) ? 1 : 0;
}

// ---------------- kernel 0c: split+transpose+interleave weights ------------
__global__ void prep_kernel(const float* __restrict__ W1,
                            const float* __restrict__ W2) {
    int i = blockIdx.x * blockDim.x + threadIdx.x;
    if (i < NC1 * 128 * 16) {
        int c = i >> 11;
        int n = (i >> 4) & 127;
        int k = i & 15;
        float w = W1[(c * 16 + k) * 128 + n];
        unsigned short h;
        asm("cvt.rn.bf16.f32 %0, %1;" : "=h"(h) : "f"(w));
        float hf = __uint_as_float(((uint32_t)h) << 16);
        float l = w - hf;
        unsigned short lo;
        asm("cvt.rn.bf16.f32 %0, %1;" : "=h"(lo) : "f"(l));
        unsigned short* row = Bexp1 + ((size_t)c * 128 + n) * 56;
        row[k] = h; row[16 + k] = lo; row[32 + k] = h;
    }
    if (i < NC2 * 128 * 16) {
        int c = i >> 11;
        int n = (i >> 4) & 127;
        int k = i & 15;
        float w = W2[(c * 16 + k) * 128 + n];
        unsigned short h;
        asm("cvt.rn.bf16.f32 %0, %1;" : "=h"(h) : "f"(w));
        float hf = __uint_as_float(((uint32_t)h) << 16);
        float l = w - hf;
        unsigned short lo;
        asm("cvt.rn.bf16.f32 %0, %1;" : "=h"(lo) : "f"(l));
        unsigned short* row = Bexp2 + ((size_t)c * 128 + n) * 56;
        row[k] = h; row[16 + k] = lo; row[32 + k] = h;
    }
}

// ---------------- kernel 1: scatter-add edges (one warp per edge) ----------
// __ldcs on edge_attr: evict-first streaming so g_sum stays L2-resident.
__global__ void scatter_kernel(const float* __restrict__ edge_attr,
                               const void* __restrict__ edge_index) {
    const int lane   = threadIdx.x & 31;
    const int warp   = (blockIdx.x * blockDim.x + threadIdx.x) >> 5;
    const int nwarps = (gridDim.x * blockDim.x) >> 5;
    const int is64   = g_is64;
    const long long* ei64 = (const long long*)edge_index;
    const int*       ei32 = (const int*)edge_index;

    for (int e = warp; e < E_EDGES; e += nwarps) {
        int dest = 0;
        if (lane == 0)
            dest = is64 ? (int)ei64[(long long)E_EDGES + e] : ei32[E_EDGES + e];
        dest = __shfl_sync(0xffffffffu, dest, 0);

        float4 v = __ldcs((const float4*)(edge_attr + (long long)e * DD + lane * 4));
        float* p = g_sum + (long long)dest * DD + lane * 4;
        asm volatile("red.global.add.v4.f32 [%0], {%1, %2, %3, %4};"
                     :: "l"(p), "f"(v.x), "f"(v.y), "f"(v.z), "f"(v.w)
                     : "memory");
        if (lane == 0) atomicAdd(&g_cnt[dest], 1.0f);
    }
}

// ---------------- kernel 2: fused concat + 2x GEMM via mma.sync bf16 -------
// Single-sync-per-chunk software pipeline.
#define THREADS 256
#define STAGE_B 28672
#define HBASE   57344
#define CTRL    172032
#define SMEM_TOTAL (CTRL + 1024)

__global__ __launch_bounds__(THREADS, 1)
void fused_mlp_mma(const float* __restrict__ x,
                   const float* __restrict__ u,
                   const float* __restrict__ b1,
                   const float* __restrict__ b2,
                   const void*  __restrict__ batch_ptr,
                   float* __restrict__ out) {
    extern __shared__ char smem[];
    const uint32_t sbase = smem_u32(smem);
    const int tid   = threadIdx.x;
    const int wid   = tid >> 5;
    const int lane  = tid & 31;
    const int warpM = wid >> 1;
    const int warpN = wid & 1;
    const int gm0   = blockIdx.x * 128;

    float* b1s = (float*)(smem + CTRL);
    float* b2s = (float*)(smem + CTRL + 512);
    if (tid < 128) b1s[tid] = b1[tid];
    else b2s[tid - 128] = b2[tid - 128];

    // ---- per-thread A-fill mapping: row = tid>>1, k-half = tid&1 ----
    const int fr = tid >> 1;
    const int hh = tid & 1;
    const int fm = gm0 + fr;
    const bool valid = fm < M_NODES;
    float inv = 1.0f;
    long long ub = 0;
    if (valid) {
        inv = 1.0f / fmaxf(g_cnt[fm], 1.0f);
        ub  = g_is64 ? ((const long long*)batch_ptr)[fm]
                     : (long long)((const int*)batch_ptr)[fm];
    }
    const uint32_t a_fill_off = (uint32_t)fr * ROWP + hh * 16;

    // ---- ldmatrix lane offsets ----
    const uint32_t a_lane = ((lane & 7) + 8 * ((lane >> 3) & 1)) * ROWP +
                            (lane >> 4) * 16;
    const uint32_t b_lane = ((lane & 7) + 8 * (lane >> 4)) * ROWP +
                            ((lane >> 3) & 1) * 16;

    // A gather (registers only — LDG issued early, split deferred)
    auto load_A = [&](int c, float4& v0, float4& v1) {
        v0 = make_float4(0.f, 0.f, 0.f, 0.f); v1 = v0;
        if (valid) {
            const float* src;
            if (c < 8) src = x + (long long)fm * DD + c * 16 + hh * 8;
            else if (c < 16) src = g_sum + (long long)fm * DD + (c - 8) * 16 + hh * 8;
            else src = u + ub * DD + (c - 16) * 16 + hh * 8;
            v0 = ((const float4*)src)[0];
            v1 = ((const float4*)src)[1];
            if (c >= 8 && c < 16) {
                v0.x *= inv; v0.y *= inv; v0.z *= inv; v0.w *= inv;
                v1.x *= inv; v1.y *= inv; v1.z *= inv; v1.w *= inv;
            }
        }
    };
    auto store_A = [&](float4 v0, float4 v1, uint32_t stage) {
        uint4 hp, lp;
        split2(v0.x, v0.y, hp.x, lp.x);
        split2(v0.z, v0.w, hp.y, lp.y);
        split2(v1.x, v1.y, hp.z, lp.z);
        split2(v1.z, v1.w, hp.w, lp.w);
        char* dst = smem + stage + a_fill_off;
        *(uint4*)(dst)      = hp;   // slice 0 (hi)
        *(uint4*)(dst + 32) = hp;   // slice 1 (hi)
        *(uint4*)(dst + 64) = lp;   // slice 2 (lo)
    };
    // B-fill: 16B cp.async copies of pre-interleaved weights (96B per row used)
    auto fill_B = [&](const unsigned short* Bsrc, int c, uint32_t stage_b) {
        const char* base = (const char*)(Bsrc + (size_t)c * 128 * 56);
        #pragma unroll
        for (int i = 0; i < 3; i++) {
            int seg = tid + i * THREADS;         // 0..767
            int row = seg / 6, off = (seg % 6) * 16;
            CP16(sbase + stage_b + row * ROWP + off, base + row * ROWP + off);
        }
    };

    float acc[2][8][4];
    #pragma unroll
    for (int mt = 0; mt < 2; mt++)
        #pragma unroll
        for (int nt = 0; nt < 8; nt++)
            #pragma unroll
            for (int e = 0; e < 4; e++) acc[mt][nt][e] = 0.f;

    auto compute = [&](uint32_t Aoff, uint32_t Boff) {
        #pragma unroll
        for (int s = 0; s < 3; s++) {
            uint32_t a0[4], a1[4], bf[4][4];
            LDM_X4(a0[0], a0[1], a0[2], a0[3],
                   sbase + Aoff + (warpM * 32 + 0) * ROWP + a_lane + s * 32);
            LDM_X4(a1[0], a1[1], a1[2], a1[3],
                   sbase + Aoff + (warpM * 32 + 16) * ROWP + a_lane + s * 32);
            #pragma unroll
            for (int p = 0; p < 4; p++)
                LDM_X4(bf[p][0], bf[p][1], bf[p][2], bf[p][3],
                       sbase + Boff + (warpN * 64 + p * 16) * ROWP + b_lane + s * 32);
            #pragma unroll
            for (int nt = 0; nt < 8; nt++) {
                uint32_t bb0 = bf[nt >> 1][(nt & 1) * 2];
                uint32_t bb1 = bf[nt >> 1][(nt & 1) * 2 + 1];
                MMA_BF16(acc[0][nt], a0, bb0, bb1);
                MMA_BF16(acc[1][nt], a1, bb0, bb1);
            }
        }
    };

    // ================= GEMM1 (single sync per chunk) =================
    {
        float4 v0, v1;
        fill_B(Bexp1, 0, 0 + TILE_B); CP_COMMIT();
        load_A(0, v0, v1);
        store_A(v0, v1, 0);
        CP_WAIT0();
        __syncthreads();
    }
    #pragma unroll 1
    for (int c = 0; c < NC1; c++) {
        const uint32_t st  = (uint32_t)(c & 1) * STAGE_B;
        const uint32_t nst = (uint32_t)((c + 1) & 1) * STAGE_B;
        float4 v0, v1;
        const bool more = (c + 1 < NC1);
        if (more) {
            fill_B(Bexp1, c + 1, nst + TILE_B); CP_COMMIT();
            load_A(c + 1, v0, v1);               // LDG in flight under compute
        }
        compute(st, st + TILE_B);
        if (more) store_A(v0, v1, nst);
        CP_WAIT0();
        __syncthreads();
    }

    // ============ epilogue 1: H = relu(D1+b1) -> H region (expanded) =======
    // prefetch B2 chunks 0,1 into 4-slot ring (slot s at s*TILE_B)
    fill_B(Bexp2, 0, 0 * TILE_B); CP_COMMIT();
    fill_B(Bexp2, 1, 1 * TILE_B); CP_COMMIT();

    #pragma unroll
    for (int mt = 0; mt < 2; mt++) {
        #pragma unroll
        for (int nt = 0; nt < 8; nt++) {
            int col = warpN * 64 + nt * 8 + (lane & 3) * 2;
            float bv0 = b1s[col], bv1 = b1s[col + 1];
            int cch = col >> 4, k0 = col & 15;
            uint32_t hb = HBASE + cch * TILE_B + k0 * 2;
            #pragma unroll
            for (int rr = 0; rr < 2; rr++) {
                int row = warpM * 32 + mt * 16 + (lane >> 2) + rr * 8;
                float h0 = fmaxf(acc[mt][nt][rr * 2 + 0] + bv0, 0.f);
                float h1 = fmaxf(acc[mt][nt][rr * 2 + 1] + bv1, 0.f);
                uint32_t hp, lp;
                split2(h0, h1, hp, lp);
                char* dst = smem + hb + row * ROWP;
                *(uint32_t*)(dst)      = hp;
                *(uint32_t*)(dst + 32) = hp;
                *(uint32_t*)(dst + 64) = lp;
                acc[mt][nt][rr * 2 + 0] = 0.f;
                acc[mt][nt][rr * 2 + 1] = 0.f;
            }
        }
    }
    CP_WAIT1();                 // B2 chunk 0 arrived
    __syncthreads();            // H + slot0 visible

    // ================= GEMM2: 4-slot B ring, single sync per chunk ========
    #pragma unroll 1
    for (int c = 0; c < NC2; c++) {
        const bool more = (c + 2 < NC2);
        if (more) { fill_B(Bexp2, c + 2, (uint32_t)((c + 2) & 3) * TILE_B); CP_COMMIT(); }
        compute(HBASE + c * TILE_B, (uint32_t)(c & 3) * TILE_B);
        if (more) CP_WAIT1(); else CP_WAIT0();
        __syncthreads();
    }

    // ============ epilogue 2: out = D2 + b2 ============
    #pragma unroll
    for (int mt = 0; mt < 2; mt++) {
        #pragma unroll
        for (int nt = 0; nt < 8; nt++) {
            int col = warpN * 64 + nt * 8 + (lane & 3) * 2;
            float bv0 = b2s[col], bv1 = b2s[col + 1];
            #pragma unroll
            for (int rr = 0; rr < 2; rr++) {
                int m = gm0 + warpM * 32 + mt * 16 + (lane >> 2) + rr * 8;
                if (m < M_NODES) {
                    float2 o = make_float2(acc[mt][nt][rr * 2 + 0] + bv0,
                                           acc[mt][nt][rr * 2 + 1] + bv1);
                    *(float2*)(out + (long long)m * DD + col) = o;
                }
            }
        }
    }
}

// ---------------- host launcher --------------------------------------------
extern "C" void kernel_launch(void* const* d_in, const int* in_sizes, int n_in,
                              void* d_out, int out_size) {
    const float* x         = (const float*)d_in[0];
    const float* edge_attr = (const float*)d_in[1];
    const float* u         = (const float*)d_in[2];
    const float* W1        = (const float*)d_in[3];
    const float* b1        = (const float*)d_in[4];
    const float* W2        = (const float*)d_in[5];
    const float* b2        = (const float*)d_in[6];
    const void*  edge_index = d_in[7];
    const void*  batch      = d_in[8];
    float* out = (float*)d_out;

    static bool attr_set = false;
    if (!attr_set) {
        cudaFuncSetAttribute(fused_mlp_mma,
                             cudaFuncAttributeMaxDynamicSharedMemorySize,
                             SMEM_TOTAL);
        attr_set = true;
    }

    zero_kernel<<<2048, 256>>>();
    detect_kernel<<<1, 256>>>((const unsigned int*)edge_index);
    prep_kernel<<<192, 256>>>(W1, W2);
    scatter_kernel<<<1184, 256>>>(edge_attr, edge_index);

    int nblocks = (M_NODES + 127) / 128;  // 782
    fused_mlp_mma<<<nblocks, THREADS, SMEM_TOTAL>>>(x, u, b1, b2, batch, out);
}

// round 6
// speedup vs baseline: 2.1765x; 1.2384x over previous
#include <cuda_runtime.h>
#include <cuda_bf16.h>
#include <cstdint>

#define M_NODES 100000
#define DD      128
#define E_EDGES 1600000
#define NGRAPH  16

#define NC1 24      // GEMM1 chunks (384/16)
#define NC2 8       // GEMM2 chunks (128/16)
#define TILE 8192   // 128 rows * 64B (2 slices x 16 bf16), swizzled
#define STAGE 16384 // A tile + B tile

// ---------------- device scratch (static: allocation-free) ----------------
__device__ __align__(16) float g_sum[(size_t)M_NODES * DD];
__device__ float g_cnt[M_NODES];
__device__ int   g_is64;
// pre-split, pre-transposed weights: per chunk, per n-row: 16 bf16 hi, 16 bf16 lo
__device__ __align__(16) unsigned short Bexp1[NC1 * 128 * 32];
__device__ __align__(16) unsigned short Bexp2[NC2 * 128 * 32];

// ---------------- PTX helpers ----------------------------------------------
__device__ __forceinline__ uint32_t smem_u32(const void* p) {
    uint32_t a;
    asm("{ .reg .u64 t; cvta.to.shared.u64 t, %1; cvt.u32.u64 %0, t; }"
        : "=r"(a) : "l"(p));
    return a;
}
#define CP16(dst, src) \
    asm volatile("cp.async.ca.shared.global [%0], [%1], 16;" :: "r"(dst), "l"(src))
#define CP_COMMIT() asm volatile("cp.async.commit_group;" ::: "memory")
#define CP_WAIT1()  asm volatile("cp.async.wait_group 1;" ::: "memory")
#define CP_WAIT0()  asm volatile("cp.async.wait_group 0;" ::: "memory")
#define LDM_X4(r0, r1, r2, r3, a) \
    asm volatile("ldmatrix.sync.aligned.m8n8.x4.shared.b16 {%0,%1,%2,%3}, [%4];" \
                 : "=r"(r0), "=r"(r1), "=r"(r2), "=r"(r3) : "r"(a))
#define MMA_BF16(d, a, b0, b1) \
    asm volatile("mma.sync.aligned.m16n8k16.row.col.f32.bf16.bf16.f32 " \
                 "{%0,%1,%2,%3}, {%4,%5,%6,%7}, {%8,%9}, {%0,%1,%2,%3};" \
                 : "+f"((d)[0]), "+f"((d)[1]), "+f"((d)[2]), "+f"((d)[3]) \
                 : "r"((a)[0]), "r"((a)[1]), "r"((a)[2]), "r"((a)[3]), \
                   "r"(b0), "r"(b1))

// split pair of fp32 into packed bf16x2 hi + lo (mem order: v0 low)
__device__ __forceinline__ void split2(float v0, float v1,
                                       uint32_t& hp, uint32_t& lp) {
    uint32_t h2;
    asm("cvt.rn.bf16x2.f32 %0, %1, %2;" : "=r"(h2) : "f"(v1), "f"(v0));
    float h0 = __uint_as_float(h2 << 16);
    float h1 = __uint_as_float(h2 & 0xFFFF0000u);
    float l0 = v0 - h0, l1 = v1 - h1;
    asm("cvt.rn.bf16x2.f32 %0, %1, %2;" : "=r"(lp) : "f"(l1), "f"(l0));
    hp = h2;
}

// ---------------- kernel 0: zero the accumulators --------------------------
__global__ void zero_kernel() {
    const int stride = gridDim.x * blockDim.x;
    int t = blockIdx.x * blockDim.x + threadIdx.x;
    float4 z = make_float4(0.f, 0.f, 0.f, 0.f);
    const int n4 = M_NODES * DD / 4;
    for (int i = t; i < n4; i += stride) ((float4*)g_sum)[i] = z;
    for (int i = t; i < M_NODES; i += stride) g_cnt[i] = 0.0f;
}

// ---------------- kernel 0b: detect int64 vs int32 index dtype -------------
__global__ void detect_kernel(const unsigned int* ei_words) {
    __shared__ unsigned int s;
    if (threadIdx.x == 0) s = 0u;
    __syncthreads();
    unsigned int v = 0u;
    for (int i = threadIdx.x; i < 8192; i += blockDim.x) v |= ei_words[2 * i + 1];
    atomicOr(&s, v);
    __syncthreads();
    if (threadIdx.x == 0) g_is64 = (s == 0u) ? 1 : 0;
}

// ---------------- kernel 0c: split+transpose weights -----------------------
__global__ void prep_kernel(const float* __restrict__ W1,
                            const float* __restrict__ W2) {
    int i = blockIdx.x * blockDim.x + threadIdx.x;
    if (i < NC1 * 128 * 16) {
        int c = i >> 11, n = (i >> 4) & 127, k = i & 15;
        float w = W1[(c * 16 + k) * 128 + n];
        unsigned short h;
        asm("cvt.rn.bf16.f32 %0, %1;" : "=h"(h) : "f"(w));
        float l = w - __uint_as_float(((uint32_t)h) << 16);
        unsigned short lo;
        asm("cvt.rn.bf16.f32 %0, %1;" : "=h"(lo) : "f"(l));
        unsigned short* row = Bexp1 + ((size_t)c * 128 + n) * 32;
        row[k] = h; row[16 + k] = lo;
    }
    if (i < NC2 * 128 * 16) {
        int c = i >> 11, n = (i >> 4) & 127, k = i & 15;
        float w = W2[(c * 16 + k) * 128 + n];
        unsigned short h;
        asm("cvt.rn.bf16.f32 %0, %1;" : "=h"(h) : "f"(w));
        float l = w - __uint_as_float(((uint32_t)h) << 16);
        unsigned short lo;
        asm("cvt.rn.bf16.f32 %0, %1;" : "=h"(lo) : "f"(l));
        unsigned short* row = Bexp2 + ((size_t)c * 128 + n) * 32;
        row[k] = h; row[16 + k] = lo;
    }
}

// ---------------- kernel 1: scatter-add edges (one warp per edge) ----------
__global__ void scatter_kernel(const float* __restrict__ edge_attr,
                               const void* __restrict__ edge_index) {
    const int lane   = threadIdx.x & 31;
    const int warp   = (blockIdx.x * blockDim.x + threadIdx.x) >> 5;
    const int nwarps = (gridDim.x * blockDim.x) >> 5;
    const int is64   = g_is64;
    const long long* ei64 = (const long long*)edge_index;
    const int*       ei32 = (const int*)edge_index;

    for (int e = warp; e < E_EDGES; e += nwarps) {
        int dest = 0;
        if (lane == 0)
            dest = is64 ? (int)ei64[(long long)E_EDGES + e] : ei32[E_EDGES + e];
        dest = __shfl_sync(0xffffffffu, dest, 0);

        float4 v = __ldcs((const float4*)(edge_attr + (long long)e * DD + lane * 4));
        float* p = g_sum + (long long)dest * DD + lane * 4;
        asm volatile("red.global.add.v4.f32 [%0], {%1, %2, %3, %4};"
                     :: "l"(p), "f"(v.x), "f"(v.y), "f"(v.z), "f"(v.w)
                     : "memory");
        if (lane == 0) atomicAdd(&g_cnt[dest], 1.0f);
    }
}

// ---------------- kernel 2: fused concat + 2x GEMM via mma.sync bf16 -------
// 2-slice swizzled tiles (64B pitch), 2 CTAs/SM, register-dedup 3-product split.
#define THREADS 256
#define HBASE   32768
#define CTRL    98304
#define SMEM_TOTAL (CTRL + 1024)

__global__ __launch_bounds__(THREADS, 2)
void fused_mlp_mma(const float* __restrict__ x,
                   const float* __restrict__ u,
                   const float* __restrict__ b1,
                   const float* __restrict__ b2,
                   const void*  __restrict__ batch_ptr,
                   float* __restrict__ out) {
    extern __shared__ char smem[];
    const uint32_t sbase = smem_u32(smem);
    const int tid   = threadIdx.x;
    const int wid   = tid >> 5;
    const int lane  = tid & 31;
    const int warpM = wid >> 1;
    const int warpN = wid & 1;
    const int gm0   = blockIdx.x * 128;

    float* b1s = (float*)(smem + CTRL);
    float* b2s = (float*)(smem + CTRL + 512);
    if (tid < 128) b1s[tid] = b1[tid];
    else b2s[tid - 128] = b2[tid - 128];

    // ---- A-fill mapping: row = tid>>1, k-half = tid&1 ----
    const int fr = tid >> 1;
    const int hh = tid & 1;
    const int fm = gm0 + fr;
    const bool valid = fm < M_NODES;
    float inv = 1.0f;
    long long ub = 0;
    if (valid) {
        inv = 1.0f / fmaxf(g_cnt[fm], 1.0f);
        ub  = g_is64 ? ((const long long*)batch_ptr)[fm]
                     : (long long)((const int*)batch_ptr)[fm];
    }
    const int fsw = (fr >> 1) & 3;
    const uint32_t a_dst_hi = (uint32_t)fr * 64 + (uint32_t)((hh ^ fsw) << 4);
    const uint32_t a_dst_lo = (uint32_t)fr * 64 + (uint32_t)(((hh + 2) ^ fsw) << 4);

    // ---- ldmatrix per-lane offsets (swizzled) ----
    const int arow = (lane & 7) + 8 * ((lane >> 3) & 1);
    const int ac   = lane >> 4;
    const int asw  = (arow >> 1) & 3;
    const uint32_t aoff_hi = (uint32_t)arow * 64 + (uint32_t)((ac ^ asw) << 4);
    const uint32_t aoff_lo = (uint32_t)arow * 64 + (uint32_t)(((ac + 2) ^ asw) << 4);
    const int brow = (lane & 7) + 8 * (lane >> 4);
    const int bc   = (lane >> 3) & 1;
    const int bsw  = (brow >> 1) & 3;
    const uint32_t boff_hi = (uint32_t)brow * 64 + (uint32_t)((bc ^ bsw) << 4);
    const uint32_t boff_lo = (uint32_t)brow * 64 + (uint32_t)(((bc + 2) ^ bsw) << 4);

    auto load_A = [&](int c, float4& v0, float4& v1) {
        v0 = make_float4(0.f, 0.f, 0.f, 0.f); v1 = v0;
        if (valid) {
            const float* src;
            if (c < 8) src = x + (long long)fm * DD + c * 16 + hh * 8;
            else if (c < 16) src = g_sum + (long long)fm * DD + (c - 8) * 16 + hh * 8;
            else src = u + ub * DD + (c - 16) * 16 + hh * 8;
            v0 = ((const float4*)src)[0];
            v1 = ((const float4*)src)[1];
            if (c >= 8 && c < 16) {
                v0.x *= inv; v0.y *= inv; v0.z *= inv; v0.w *= inv;
                v1.x *= inv; v1.y *= inv; v1.z *= inv; v1.w *= inv;
            }
        }
    };
    auto store_A = [&](float4 v0, float4 v1, uint32_t stage) {
        uint4 hp, lp;
        split2(v0.x, v0.y, hp.x, lp.x);
        split2(v0.z, v0.w, hp.y, lp.y);
        split2(v1.x, v1.y, hp.z, lp.z);
        split2(v1.z, v1.w, hp.w, lp.w);
        *(uint4*)(smem + stage + a_dst_hi) = hp;
        *(uint4*)(smem + stage + a_dst_lo) = lp;
    };
    auto fill_B = [&](const unsigned short* Bsrc, int c, uint32_t dstb) {
        const char* base = (const char*)(Bsrc + (size_t)c * 128 * 32);
        #pragma unroll
        for (int i = 0; i < 2; i++) {
            int seg = tid + i * THREADS;           // 0..511
            int row = seg >> 2, cc = seg & 3;
            int sw = cc ^ ((row >> 1) & 3);
            CP16(sbase + dstb + row * 64 + sw * 16, base + row * 64 + cc * 16);
        }
    };

    float acc[2][8][4];
    #pragma unroll
    for (int mt = 0; mt < 2; mt++)
        #pragma unroll
        for (int nt = 0; nt < 8; nt++)
            #pragma unroll
            for (int e = 0; e < 4; e++) acc[mt][nt][e] = 0.f;

    auto compute = [&](uint32_t Aoff, uint32_t Boff) {
        uint32_t Ah[2][4], Al[2][4];
        #pragma unroll
        for (int mt = 0; mt < 2; mt++) {
            uint32_t ab = sbase + Aoff + (uint32_t)(warpM * 32 + mt * 16) * 64;
            LDM_X4(Ah[mt][0], Ah[mt][1], Ah[mt][2], Ah[mt][3], ab + aoff_hi);
            LDM_X4(Al[mt][0], Al[mt][1], Al[mt][2], Al[mt][3], ab + aoff_lo);
        }
        uint32_t Bh[2][4], Bl[2][4];
        {
            uint32_t bb = sbase + Boff + (uint32_t)(warpN * 64) * 64;
            LDM_X4(Bh[0][0], Bh[0][1], Bh[0][2], Bh[0][3], bb + boff_hi);
            LDM_X4(Bl[0][0], Bl[0][1], Bl[0][2], Bl[0][3], bb + boff_lo);
        }
        #pragma unroll
        for (int p = 0; p < 4; p++) {
            const int cur = p & 1, nxt = cur ^ 1;
            if (p < 3) {
                uint32_t bb = sbase + Boff + (uint32_t)(warpN * 64 + (p + 1) * 16) * 64;
                LDM_X4(Bh[nxt][0], Bh[nxt][1], Bh[nxt][2], Bh[nxt][3], bb + boff_hi);
                LDM_X4(Bl[nxt][0], Bl[nxt][1], Bl[nxt][2], Bl[nxt][3], bb + boff_lo);
            }
            #pragma unroll
            for (int q = 0; q < 2; q++) {
                const int nt = p * 2 + q;
                uint32_t bh0 = Bh[cur][q * 2], bh1 = Bh[cur][q * 2 + 1];
                uint32_t bl0 = Bl[cur][q * 2], bl1 = Bl[cur][q * 2 + 1];
                #pragma unroll
                for (int mt = 0; mt < 2; mt++) {
                    MMA_BF16(acc[mt][nt], Ah[mt], bh0, bh1);
                    MMA_BF16(acc[mt][nt], Ah[mt], bl0, bl1);
                    MMA_BF16(acc[mt][nt], Al[mt], bh0, bh1);
                }
            }
        }
    };

    // ================= GEMM1 (single sync per chunk) =================
    {
        float4 v0, v1;
        fill_B(Bexp1, 0, 0 + TILE); CP_COMMIT();
        load_A(0, v0, v1);
        store_A(v0, v1, 0);
        CP_WAIT0();
        __syncthreads();
    }
    #pragma unroll 1
    for (int c = 0; c < NC1; c++) {
        const uint32_t st  = (uint32_t)(c & 1) * STAGE;
        const uint32_t nst = (uint32_t)((c + 1) & 1) * STAGE;
        float4 v0, v1;
        const bool more = (c + 1 < NC1);
        if (more) {
            fill_B(Bexp1, c + 1, nst + TILE); CP_COMMIT();
            load_A(c + 1, v0, v1);
        }
        compute(st, st + TILE);
        if (more) store_A(v0, v1, nst);
        CP_WAIT0();
        __syncthreads();
    }

    // ============ epilogue 1: H = relu(D1+b1) -> H region ============
    fill_B(Bexp2, 0, 0 * TILE); CP_COMMIT();
    fill_B(Bexp2, 1, 1 * TILE); CP_COMMIT();

    #pragma unroll
    for (int mt = 0; mt < 2; mt++) {
        #pragma unroll
        for (int nt = 0; nt < 8; nt++) {
            int col = warpN * 64 + nt * 8 + (lane & 3) * 2;
            float bv0 = b1s[col], bv1 = b1s[col + 1];
            int cch = col >> 4, k0 = col & 15;
            int chi = k0 >> 3, kb = (k0 & 7) * 2;
            #pragma unroll
            for (int rr = 0; rr < 2; rr++) {
                int row = warpM * 32 + mt * 16 + (lane >> 2) + rr * 8;
                float h0 = fmaxf(acc[mt][nt][rr * 2 + 0] + bv0, 0.f);
                float h1 = fmaxf(acc[mt][nt][rr * 2 + 1] + bv1, 0.f);
                uint32_t hp, lp;
                split2(h0, h1, hp, lp);
                int sw = (row >> 1) & 3;
                char* dst = smem + HBASE + cch * TILE + row * 64;
                *(uint32_t*)(dst + ((chi ^ sw) << 4) + kb)       = hp;
                *(uint32_t*)(dst + (((chi + 2) ^ sw) << 4) + kb) = lp;
                acc[mt][nt][rr * 2 + 0] = 0.f;
                acc[mt][nt][rr * 2 + 1] = 0.f;
            }
        }
    }
    CP_WAIT1();
    __syncthreads();

    // ================= GEMM2: 4-slot B ring =================
    #pragma unroll 1
    for (int c = 0; c < NC2; c++) {
        const bool more = (c + 2 < NC2);
        if (more) { fill_B(Bexp2, c + 2, (uint32_t)((c + 2) & 3) * TILE); CP_COMMIT(); }
        compute(HBASE + c * TILE, (uint32_t)(c & 3) * TILE);
        if (more) CP_WAIT1(); else CP_WAIT0();
        __syncthreads();
    }

    // ============ epilogue 2: out = D2 + b2 ============
    #pragma unroll
    for (int mt = 0; mt < 2; mt++) {
        #pragma unroll
        for (int nt = 0; nt < 8; nt++) {
            int col = warpN * 64 + nt * 8 + (lane & 3) * 2;
            float bv0 = b2s[col], bv1 = b2s[col + 1];
            #pragma unroll
            for (int rr = 0; rr < 2; rr++) {
                int m = gm0 + warpM * 32 + mt * 16 + (lane >> 2) + rr * 8;
                if (m < M_NODES) {
                    float2 o = make_float2(acc[mt][nt][rr * 2 + 0] + bv0,
                                           acc[mt][nt][rr * 2 + 1] + bv1);
                    *(float2*)(out + (long long)m * DD + col) = o;
                }
            }
        }
    }
}

// ---------------- host launcher --------------------------------------------
extern "C" void kernel_launch(void* const* d_in, const int* in_sizes, int n_in,
                              void* d_out, int out_size) {
    const float* x         = (const float*)d_in[0];
    const float* edge_attr = (const float*)d_in[1];
    const float* u         = (const float*)d_in[2];
    const float* W1        = (const float*)d_in[3];
    const float* b1        = (const float*)d_in[4];
    const float* W2        = (const float*)d_in[5];
    const float* b2        = (const float*)d_in[6];
    const void*  edge_index = d_in[7];
    const void*  batch      = d_in[8];
    float* out = (float*)d_out;

    static bool attr_set = false;
    if (!attr_set) {
        cudaFuncSetAttribute(fused_mlp_mma,
                             cudaFuncAttributeMaxDynamicSharedMemorySize,
                             SMEM_TOTAL);
        attr_set = true;
    }

    zero_kernel<<<2048, 256>>>();
    detect_kernel<<<1, 256>>>((const unsigned int*)edge_index);
    prep_kernel<<<192, 256>>>(W1, W2);
    scatter_kernel<<<1184, 256>>>(edge_attr, edge_index);

    int nblocks = (M_NODES + 127) / 128;  // 782
    fused_mlp_mma<<<nblocks, THREADS, SMEM_TOTAL>>>(x, u, b1, b2, batch, out);
}

// round 7
// speedup vs baseline: 2.3320x; 1.0714x over previous
#include <cuda_runtime.h>
#include <cuda_bf16.h>
#include <cstdint>

#define M_NODES 100000
#define E_EDGES 1600000
#define DD      128
#define NGRAPH  16

#define NC1 24
#define NC2 8
#define TILE 8192
#define STAGE 16384

#define NB_SCAN ((M_NODES + 255) / 256)   // 391

// ---------------- device scratch (static: allocation-free) ----------------
__device__ __align__(16) float g_sum[(size_t)M_NODES * DD];
__device__ int   g_cnt_i[M_NODES];
__device__ int   g_off[M_NODES];
__device__ int   g_cur[M_NODES];
__device__ int   g_perm[E_EDGES];
__device__ int   g_bsum[512];
__device__ int   g_is64;
__device__ __align__(16) unsigned short Bexp1[NC1 * 128 * 32];
__device__ __align__(16) unsigned short Bexp2[NC2 * 128 * 32];

// ---------------- PTX helpers ----------------------------------------------
__device__ __forceinline__ uint32_t smem_u32(const void* p) {
    uint32_t a;
    asm("{ .reg .u64 t; cvta.to.shared.u64 t, %1; cvt.u32.u64 %0, t; }"
        : "=r"(a) : "l"(p));
    return a;
}
#define CP16(dst, src) \
    asm volatile("cp.async.ca.shared.global [%0], [%1], 16;" :: "r"(dst), "l"(src))
#define CP_COMMIT() asm volatile("cp.async.commit_group;" ::: "memory")
#define CP_WAIT1()  asm volatile("cp.async.wait_group 1;" ::: "memory")
#define CP_WAIT0()  asm volatile("cp.async.wait_group 0;" ::: "memory")
#define LDM_X4(r0, r1, r2, r3, a) \
    asm volatile("ldmatrix.sync.aligned.m8n8.x4.shared.b16 {%0,%1,%2,%3}, [%4];" \
                 : "=r"(r0), "=r"(r1), "=r"(r2), "=r"(r3) : "r"(a))
#define MMA_BF16(d, a, b0, b1) \
    asm volatile("mma.sync.aligned.m16n8k16.row.col.f32.bf16.bf16.f32 " \
                 "{%0,%1,%2,%3}, {%4,%5,%6,%7}, {%8,%9}, {%0,%1,%2,%3};" \
                 : "+f"((d)[0]), "+f"((d)[1]), "+f"((d)[2]), "+f"((d)[3]) \
                 : "r"((a)[0]), "r"((a)[1]), "r"((a)[2]), "r"((a)[3]), \
                   "r"(b0), "r"(b1))

__device__ __forceinline__ void split2(float v0, float v1,
                                       uint32_t& hp, uint32_t& lp) {
    uint32_t h2;
    asm("cvt.rn.bf16x2.f32 %0, %1, %2;" : "=r"(h2) : "f"(v1), "f"(v0));
    float h0 = __uint_as_float(h2 << 16);
    float h1 = __uint_as_float(h2 & 0xFFFF0000u);
    float l0 = v0 - h0, l1 = v1 - h1;
    asm("cvt.rn.bf16x2.f32 %0, %1, %2;" : "=r"(lp) : "f"(l1), "f"(l0));
    hp = h2;
}
__device__ __forceinline__ int edge_dest(const void* ei, int e, int is64) {
    return is64 ? (int)((const long long*)ei)[(long long)E_EDGES + e]
                : ((const int*)ei)[E_EDGES + e];
}

// ---------------- dtype detect ----------------------------------------------
__global__ void detect_kernel(const unsigned int* ei_words) {
    __shared__ unsigned int s;
    if (threadIdx.x == 0) s = 0u;
    __syncthreads();
    unsigned int v = 0u;
    for (int i = threadIdx.x; i < 8192; i += blockDim.x) v |= ei_words[2 * i + 1];
    atomicOr(&s, v);
    __syncthreads();
    if (threadIdx.x == 0) g_is64 = (s == 0u) ? 1 : 0;
}

// ---------------- CSR build: zero counts, histogram, scan, fill -------------
__global__ void zero_cnt_kernel() {
    int i = blockIdx.x * blockDim.x + threadIdx.x;
    if (i < M_NODES) g_cnt_i[i] = 0;
}
__global__ void hist_kernel(const void* __restrict__ edge_index) {
    const int is64 = g_is64;
    const int stride = gridDim.x * blockDim.x;
    for (int e = blockIdx.x * blockDim.x + threadIdx.x; e < E_EDGES; e += stride)
        atomicAdd(&g_cnt_i[edge_dest(edge_index, e, is64)], 1);
}
__global__ void scan1_kernel() {
    __shared__ int s[256];
    int i = blockIdx.x * 256 + threadIdx.x;
    int v = (i < M_NODES) ? g_cnt_i[i] : 0;
    s[threadIdx.x] = v;
    __syncthreads();
    for (int d = 128; d > 0; d >>= 1) {
        if (threadIdx.x < d) s[threadIdx.x] += s[threadIdx.x + d];
        __syncthreads();
    }
    if (threadIdx.x == 0) g_bsum[blockIdx.x] = s[0];
}
__global__ void scan2_kernel() {
    __shared__ int s[512];
    int t = threadIdx.x;
    int v = (t < NB_SCAN) ? g_bsum[t] : 0;
    s[t] = v;
    __syncthreads();
    for (int d = 1; d < 512; d <<= 1) {
        int w = (t >= d) ? s[t - d] : 0;
        __syncthreads();
        s[t] += w;
        __syncthreads();
    }
    if (t < NB_SCAN) g_bsum[t] = s[t] - v;  // exclusive
}
__global__ void scan3_kernel() {
    __shared__ int s[256];
    int i = blockIdx.x * 256 + threadIdx.x;
    int v = (i < M_NODES) ? g_cnt_i[i] : 0;
    s[threadIdx.x] = v;
    __syncthreads();
    for (int d = 1; d < 256; d <<= 1) {
        int w = (threadIdx.x >= d) ? s[threadIdx.x - d] : 0;
        __syncthreads();
        s[threadIdx.x] += w;
        __syncthreads();
    }
    if (i < M_NODES) {
        int off = g_bsum[blockIdx.x] + s[threadIdx.x] - v;  // exclusive
        g_off[i] = off;
        g_cur[i] = off;
    }
}
__global__ void fill_kernel(const void* __restrict__ edge_index) {
    const int is64 = g_is64;
    const int stride = gridDim.x * blockDim.x;
    for (int e = blockIdx.x * blockDim.x + threadIdx.x; e < E_EDGES; e += stride) {
        int d = edge_dest(edge_index, e, is64);
        int pos = atomicAdd(&g_cur[d], 1);
        g_perm[pos] = e;
    }
}

// ---------------- gather: warp per node, no atomics -------------------------
__global__ void gather_kernel(const float* __restrict__ edge_attr) {
    const int w    = (blockIdx.x * blockDim.x + threadIdx.x) >> 5;
    const int lane = threadIdx.x & 31;
    if (w >= M_NODES) return;
    const int off = g_off[w];
    const int cnt = g_cnt_i[w];
    float4 acc = make_float4(0.f, 0.f, 0.f, 0.f);
    int j = 0;
    for (; j + 4 <= cnt; j += 4) {
        int e0 = g_perm[off + j];
        int e1 = g_perm[off + j + 1];
        int e2 = g_perm[off + j + 2];
        int e3 = g_perm[off + j + 3];
        float4 v0 = __ldcs((const float4*)(edge_attr + (long long)e0 * DD + lane * 4));
        float4 v1 = __ldcs((const float4*)(edge_attr + (long long)e1 * DD + lane * 4));
        float4 v2 = __ldcs((const float4*)(edge_attr + (long long)e2 * DD + lane * 4));
        float4 v3 = __ldcs((const float4*)(edge_attr + (long long)e3 * DD + lane * 4));
        acc.x += v0.x + v1.x + v2.x + v3.x;
        acc.y += v0.y + v1.y + v2.y + v3.y;
        acc.z += v0.z + v1.z + v2.z + v3.z;
        acc.w += v0.w + v1.w + v2.w + v3.w;
    }
    for (; j < cnt; j++) {
        int e = g_perm[off + j];
        float4 v = __ldcs((const float4*)(edge_attr + (long long)e * DD + lane * 4));
        acc.x += v.x; acc.y += v.y; acc.z += v.z; acc.w += v.w;
    }
    *(float4*)(g_sum + (long long)w * DD + lane * 4) = acc;
}

// ---------------- weight prep ------------------------------------------------
__global__ void prep_kernel(const float* __restrict__ W1,
                            const float* __restrict__ W2) {
    int i = blockIdx.x * blockDim.x + threadIdx.x;
    if (i < NC1 * 128 * 16) {
        int c = i >> 11, n = (i >> 4) & 127, k = i & 15;
        float w = W1[(c * 16 + k) * 128 + n];
        unsigned short h;
        asm("cvt.rn.bf16.f32 %0, %1;" : "=h"(h) : "f"(w));
        float l = w - __uint_as_float(((uint32_t)h) << 16);
        unsigned short lo;
        asm("cvt.rn.bf16.f32 %0, %1;" : "=h"(lo) : "f"(l));
        unsigned short* row = Bexp1 + ((size_t)c * 128 + n) * 32;
        row[k] = h; row[16 + k] = lo;
    }
    if (i < NC2 * 128 * 16) {
        int c = i >> 11, n = (i >> 4) & 127, k = i & 15;
        float w = W2[(c * 16 + k) * 128 + n];
        unsigned short h;
        asm("cvt.rn.bf16.f32 %0, %1;" : "=h"(h) : "f"(w));
        float l = w - __uint_as_float(((uint32_t)h) << 16);
        unsigned short lo;
        asm("cvt.rn.bf16.f32 %0, %1;" : "=h"(lo) : "f"(l));
        unsigned short* row = Bexp2 + ((size_t)c * 128 + n) * 32;
        row[k] = h; row[16 + k] = lo;
    }
}

// ---------------- fused concat + 2x GEMM via mma.sync bf16 ------------------
#define THREADS 256
#define HBASE   32768
#define CTRL    98304
#define SMEM_TOTAL (CTRL + 1024)

__global__ __launch_bounds__(THREADS, 2)
void fused_mlp_mma(const float* __restrict__ x,
                   const float* __restrict__ u,
                   const float* __restrict__ b1,
                   const float* __restrict__ b2,
                   const void*  __restrict__ batch_ptr,
                   float* __restrict__ out) {
    extern __shared__ char smem[];
    const uint32_t sbase = smem_u32(smem);
    const int tid   = threadIdx.x;
    const int wid   = tid >> 5;
    const int lane  = tid & 31;
    const int warpM = wid >> 1;
    const int warpN = wid & 1;
    const int gm0   = blockIdx.x * 128;

    float* b1s = (float*)(smem + CTRL);
    float* b2s = (float*)(smem + CTRL + 512);
    if (tid < 128) b1s[tid] = b1[tid];
    else b2s[tid - 128] = b2[tid - 128];

    const int fr = tid >> 1;
    const int hh = tid & 1;
    const int fm = gm0 + fr;
    const bool valid = fm < M_NODES;
    float inv = 1.0f;
    long long ub = 0;
    if (valid) {
        inv = 1.0f / fmaxf((float)g_cnt_i[fm], 1.0f);
        ub  = g_is64 ? ((const long long*)batch_ptr)[fm]
                     : (long long)((const int*)batch_ptr)[fm];
    }
    const int fsw = (fr >> 1) & 3;
    const uint32_t a_dst_hi = (uint32_t)fr * 64 + (uint32_t)((hh ^ fsw) << 4);
    const uint32_t a_dst_lo = (uint32_t)fr * 64 + (uint32_t)(((hh + 2) ^ fsw) << 4);

    const int arow = (lane & 7) + 8 * ((lane >> 3) & 1);
    const int ac   = lane >> 4;
    const int asw  = (arow >> 1) & 3;
    const uint32_t aoff_hi = (uint32_t)arow * 64 + (uint32_t)((ac ^ asw) << 4);
    const uint32_t aoff_lo = (uint32_t)arow * 64 + (uint32_t)(((ac + 2) ^ asw) << 4);
    const int brow = (lane & 7) + 8 * (lane >> 4);
    const int bc   = (lane >> 3) & 1;
    const int bsw  = (brow >> 1) & 3;
    const uint32_t boff_hi = (uint32_t)brow * 64 + (uint32_t)((bc ^ bsw) << 4);
    const uint32_t boff_lo = (uint32_t)brow * 64 + (uint32_t)(((bc + 2) ^ bsw) << 4);

    auto load_A = [&](int c, float4& v0, float4& v1) {
        v0 = make_float4(0.f, 0.f, 0.f, 0.f); v1 = v0;
        if (valid) {
            const float* src;
            if (c < 8) src = x + (long long)fm * DD + c * 16 + hh * 8;
            else if (c < 16) src = g_sum + (long long)fm * DD + (c - 8) * 16 + hh * 8;
            else src = u + ub * DD + (c - 16) * 16 + hh * 8;
            v0 = ((const float4*)src)[0];
            v1 = ((const float4*)src)[1];
            if (c >= 8 && c < 16) {
                v0.x *= inv; v0.y *= inv; v0.z *= inv; v0.w *= inv;
                v1.x *= inv; v1.y *= inv; v1.z *= inv; v1.w *= inv;
            }
        }
    };
    auto store_A = [&](float4 v0, float4 v1, uint32_t stage) {
        uint4 hp, lp;
        split2(v0.x, v0.y, hp.x, lp.x);
        split2(v0.z, v0.w, hp.y, lp.y);
        split2(v1.x, v1.y, hp.z, lp.z);
        split2(v1.z, v1.w, hp.w, lp.w);
        *(uint4*)(smem + stage + a_dst_hi) = hp;
        *(uint4*)(smem + stage + a_dst_lo) = lp;
    };
    auto fill_B = [&](const unsigned short* Bsrc, int c, uint32_t dstb) {
        const char* base = (const char*)(Bsrc + (size_t)c * 128 * 32);
        #pragma unroll
        for (int i = 0; i < 2; i++) {
            int seg = tid + i * THREADS;
            int row = seg >> 2, cc = seg & 3;
            int sw = cc ^ ((row >> 1) & 3);
            CP16(sbase + dstb + row * 64 + sw * 16, base + row * 64 + cc * 16);
        }
    };

    float acc[2][8][4];
    #pragma unroll
    for (int mt = 0; mt < 2; mt++)
        #pragma unroll
        for (int nt = 0; nt < 8; nt++)
            #pragma unroll
            for (int e = 0; e < 4; e++) acc[mt][nt][e] = 0.f;

    auto compute = [&](uint32_t Aoff, uint32_t Boff) {
        uint32_t Ah[2][4], Al[2][4];
        #pragma unroll
        for (int mt = 0; mt < 2; mt++) {
            uint32_t ab = sbase + Aoff + (uint32_t)(warpM * 32 + mt * 16) * 64;
            LDM_X4(Ah[mt][0], Ah[mt][1], Ah[mt][2], Ah[mt][3], ab + aoff_hi);
            LDM_X4(Al[mt][0], Al[mt][1], Al[mt][2], Al[mt][3], ab + aoff_lo);
        }
        uint32_t Bh[2][4], Bl[2][4];
        {
            uint32_t bb = sbase + Boff + (uint32_t)(warpN * 64) * 64;
            LDM_X4(Bh[0][0], Bh[0][1], Bh[0][2], Bh[0][3], bb + boff_hi);
            LDM_X4(Bl[0][0], Bl[0][1], Bl[0][2], Bl[0][3], bb + boff_lo);
        }
        #pragma unroll
        for (int p = 0; p < 4; p++) {
            const int cur = p & 1, nxt = cur ^ 1;
            if (p < 3) {
                uint32_t bb = sbase + Boff + (uint32_t)(warpN * 64 + (p + 1) * 16) * 64;
                LDM_X4(Bh[nxt][0], Bh[nxt][1], Bh[nxt][2], Bh[nxt][3], bb + boff_hi);
                LDM_X4(Bl[nxt][0], Bl[nxt][1], Bl[nxt][2], Bl[nxt][3], bb + boff_lo);
            }
            #pragma unroll
            for (int q = 0; q < 2; q++) {
                const int nt = p * 2 + q;
                uint32_t bh0 = Bh[cur][q * 2], bh1 = Bh[cur][q * 2 + 1];
                uint32_t bl0 = Bl[cur][q * 2], bl1 = Bl[cur][q * 2 + 1];
                #pragma unroll
                for (int mt = 0; mt < 2; mt++) {
                    MMA_BF16(acc[mt][nt], Ah[mt], bh0, bh1);
                    MMA_BF16(acc[mt][nt], Ah[mt], bl0, bl1);
                    MMA_BF16(acc[mt][nt], Al[mt], bh0, bh1);
                }
            }
        }
    };

    // ================= GEMM1 =================
    {
        float4 v0, v1;
        fill_B(Bexp1, 0, 0 + TILE); CP_COMMIT();
        load_A(0, v0, v1);
        store_A(v0, v1, 0);
        CP_WAIT0();
        __syncthreads();
    }
    #pragma unroll 1
    for (int c = 0; c < NC1; c++) {
        const uint32_t st  = (uint32_t)(c & 1) * STAGE;
        const uint32_t nst = (uint32_t)((c + 1) & 1) * STAGE;
        float4 v0, v1;
        const bool more = (c + 1 < NC1);
        if (more) {
            fill_B(Bexp1, c + 1, nst + TILE); CP_COMMIT();
            load_A(c + 1, v0, v1);
        }
        compute(st, st + TILE);
        if (more) store_A(v0, v1, nst);
        CP_WAIT0();
        __syncthreads();
    }

    // ============ epilogue 1 ============
    fill_B(Bexp2, 0, 0 * TILE); CP_COMMIT();
    fill_B(Bexp2, 1, 1 * TILE); CP_COMMIT();

    #pragma unroll
    for (int mt = 0; mt < 2; mt++) {
        #pragma unroll
        for (int nt = 0; nt < 8; nt++) {
            int col = warpN * 64 + nt * 8 + (lane & 3) * 2;
            float bv0 = b1s[col], bv1 = b1s[col + 1];
            int cch = col >> 4, k0 = col & 15;
            int chi = k0 >> 3, kb = (k0 & 7) * 2;
            #pragma unroll
            for (int rr = 0; rr < 2; rr++) {
                int row = warpM * 32 + mt * 16 + (lane >> 2) + rr * 8;
                float h0 = fmaxf(acc[mt][nt][rr * 2 + 0] + bv0, 0.f);
                float h1 = fmaxf(acc[mt][nt][rr * 2 + 1] + bv1, 0.f);
                uint32_t hp, lp;
                split2(h0, h1, hp, lp);
                int sw = (row >> 1) & 3;
                char* dst = smem + HBASE + cch * TILE + row * 64;
                *(uint32_t*)(dst + ((chi ^ sw) << 4) + kb)       = hp;
                *(uint32_t*)(dst + (((chi + 2) ^ sw) << 4) + kb) = lp;
                acc[mt][nt][rr * 2 + 0] = 0.f;
                acc[mt][nt][rr * 2 + 1] = 0.f;
            }
        }
    }
    CP_WAIT1();
    __syncthreads();

    // ================= GEMM2 =================
    #pragma unroll 1
    for (int c = 0; c < NC2; c++) {
        const bool more = (c + 2 < NC2);
        if (more) { fill_B(Bexp2, c + 2, (uint32_t)((c + 2) & 3) * TILE); CP_COMMIT(); }
        compute(HBASE + c * TILE, (uint32_t)(c & 3) * TILE);
        if (more) CP_WAIT1(); else CP_WAIT0();
        __syncthreads();
    }

    // ============ epilogue 2 ============
    #pragma unroll
    for (int mt = 0; mt < 2; mt++) {
        #pragma unroll
        for (int nt = 0; nt < 8; nt++) {
            int col = warpN * 64 + nt * 8 + (lane & 3) * 2;
            float bv0 = b2s[col], bv1 = b2s[col + 1];
            #pragma unroll
            for (int rr = 0; rr < 2; rr++) {
                int m = gm0 + warpM * 32 + mt * 16 + (lane >> 2) + rr * 8;
                if (m < M_NODES) {
                    float2 o = make_float2(acc[mt][nt][rr * 2 + 0] + bv0,
                                           acc[mt][nt][rr * 2 + 1] + bv1);
                    *(float2*)(out + (long long)m * DD + col) = o;
                }
            }
        }
    }
}

// ---------------- host launcher --------------------------------------------
extern "C" void kernel_launch(void* const* d_in, const int* in_sizes, int n_in,
                              void* d_out, int out_size) {
    const float* x         = (const float*)d_in[0];
    const float* edge_attr = (const float*)d_in[1];
    const float* u         = (const float*)d_in[2];
    const float* W1        = (const float*)d_in[3];
    const float* b1        = (const float*)d_in[4];
    const float* W2        = (const float*)d_in[5];
    const float* b2        = (const float*)d_in[6];
    const void*  edge_index = d_in[7];
    const void*  batch      = d_in[8];
    float* out = (float*)d_out;

    static bool attr_set = false;
    if (!attr_set) {
        cudaFuncSetAttribute(fused_mlp_mma,
                             cudaFuncAttributeMaxDynamicSharedMemorySize,
                             SMEM_TOTAL);
        attr_set = true;
    }

    detect_kernel<<<1, 256>>>((const unsigned int*)edge_index);
    zero_cnt_kernel<<<(M_NODES + 255) / 256, 256>>>();
    prep_kernel<<<192, 256>>>(W1, W2);
    hist_kernel<<<1184, 256>>>(edge_index);
    scan1_kernel<<<NB_SCAN, 256>>>();
    scan2_kernel<<<1, 512>>>();
    scan3_kernel<<<NB_SCAN, 256>>>();
    fill_kernel<<<1184, 256>>>(edge_index);
    gather_kernel<<<(M_NODES * 32 + 255) / 256, 256>>>(edge_attr);

    int nblocks = (M_NODES + 127) / 128;  // 782
    fused_mlp_mma<<<nblocks, THREADS, SMEM_TOTAL>>>(x, u, b1, b2, batch, out);
}